// round 13
// baseline (speedup 1.0000x reference)
#include <cuda_runtime.h>
#include <cuda_bf16.h>
#include <cstdint>

// Problem constants
#define BATCH 2
#define SEQ   2048
#define EMB   1024
#define HEADS 16
#define HDIM  64
#define MTOT  (BATCH*SEQ)   // 4096

#if defined(__CUDA_ARCH_SPECIFIC__) || defined(__CUDA_ARCH_FEAT_SM103_ALL) || \
    defined(__CUDA_ARCH_FEAT_SM100_ALL) || defined(__CUDA_ARCH_FAMILY_SPECIFIC__)
#define USE_TCGEN05 1
#else
#define USE_TCGEN05 0
#endif

// Scratch (allocation-free rule: __device__ globals)
__device__ __nv_bfloat16 g_xhi[MTOT * EMB];
__device__ __nv_bfloat16 g_xlo[MTOT * EMB];
__device__ __nv_bfloat16 g_qhi[MTOT * EMB];
__device__ __nv_bfloat16 g_qlo[MTOT * EMB];
__device__ __nv_bfloat16 g_khi[MTOT * EMB];
__device__ __nv_bfloat16 g_klo[MTOT * EMB];
__device__ __nv_bfloat16 g_vthi[MTOT * EMB];  // [b][h][d][s] (written by V GEMM epilogue)
__device__ __nv_bfloat16 g_vtlo[MTOT * EMB];
__device__ __nv_bfloat16 g_chi[MTOT * EMB];   // attention output (ctx) hi/lo
__device__ __nv_bfloat16 g_clo[MTOT * EMB];
__device__ __nv_bfloat16 g_wthi[4][EMB * EMB];   // W^T hi (q,k,v,o)
__device__ __nv_bfloat16 g_wtlo[4][EMB * EMB];

// GEMM: 128x128 tile, KC=32 chunks ping-pong between byte-column halves of one
// SW128 tile per operand. SMEM: Ahi 16K | Alo 16K | Bhi 16K | Blo 16K = 64K.
#define G_TILE   16384
#define GEMM_TILES 65536
#define SMEM_DYN (1024 + GEMM_TILES + 64)

// Attention SMEM: Q hi/lo 32K + K 2-ring (16K/stage) + V 2-ring (16K/stage)
#define AT_TILES 98304
#define AT_SMEM  (1024 + AT_TILES + 64)

#if USE_TCGEN05
// ---------------------------------------------------------------------------
// PTX helpers (sm_103a only)
// ---------------------------------------------------------------------------
__device__ __forceinline__ uint32_t smem_u32(const void* p) {
    uint32_t a;
    asm("{ .reg .u64 t; cvta.to.shared.u64 t, %1; cvt.u32.u64 %0, t; }" : "=r"(a) : "l"(p));
    return a;
}
__device__ __forceinline__ uint32_t elect_one() {
    uint32_t pred;
    asm volatile("{\n\t.reg .pred p;\n\telect.sync _|p, 0xFFFFFFFF;\n\t"
                 "selp.b32 %0, 1, 0, p;\n\t}" : "=r"(pred));
    return pred;
}
#define SMEM_SWZ128(off) ((off) ^ (((off) >> 3) & 0x70))

static constexpr uint64_t DESC_BASE_SW128 =
    (uint64_t(2) << 61) | (uint64_t(1) << 46) | (uint64_t(64) << 32) | (uint64_t(1) << 16);
#define MAKE_DESC(addr) (DESC_BASE_SW128 | ((uint64_t)((addr) >> 4) & 0x3FFF))

#define TC_ALLOC(sdst, n) \
    asm volatile("tcgen05.alloc.cta_group::1.sync.aligned.shared::cta.b32 [%0], %1;" \
                 :: "r"((uint32_t)(sdst)), "r"((uint32_t)(n)) : "memory")
#define TC_DEALLOC(t, n) \
    asm volatile("tcgen05.dealloc.cta_group::1.sync.aligned.b32 %0, %1;" :: "r"(t), "r"(n))
#define TC_RELINQ() \
    asm volatile("tcgen05.relinquish_alloc_permit.cta_group::1.sync.aligned;")
#define TC_COMMIT(mb) \
    asm volatile("tcgen05.commit.cta_group::1.mbarrier::arrive::one.shared::cluster.b64 [%0];" \
                 :: "r"((uint32_t)(mb)) : "memory")
#define TC_FENCE_AFTER()  asm volatile("tcgen05.fence::after_thread_sync;" ::: "memory")
#define TC_FENCE_BEFORE() asm volatile("tcgen05.fence::before_thread_sync;" ::: "memory")
#define TC_WAIT_LD()      asm volatile("tcgen05.wait::ld.sync.aligned;" ::: "memory")
#define TC_WAIT_ST()      asm volatile("tcgen05.wait::st.sync.aligned;" ::: "memory")
#define FENCE_ASYNC()     asm volatile("fence.proxy.async.shared::cta;" ::: "memory")
#define MBAR_INIT(mb, c) \
    asm volatile("mbarrier.init.shared.b64 [%0], %1;" :: "r"((uint32_t)(mb)), "r"((uint32_t)(c)) : "memory")
#define MBAR_INVAL(mb) \
    asm volatile("mbarrier.inval.shared.b64 [%0];" :: "r"((uint32_t)(mb)) : "memory")

#define MBAR_WAIT(mb, ph) do {                                                    \
    uint32_t _m = (uint32_t)(mb), _p = (uint32_t)(ph), _d;                        \
    asm volatile("{\n\t.reg .pred p;\n\t"                                         \
        "mbarrier.try_wait.parity.acquire.cta.shared::cta.b64 p, [%1], %2;\n\t"   \
        "selp.b32 %0, 1, 0, p;\n\t}" : "=r"(_d) : "r"(_m), "r"(_p) : "memory");   \
    if (!_d) {                                                                    \
        asm volatile("{\n\t.reg .pred P1;\n\t"                                    \
            "WL_%=:\n\t"                                                          \
            "mbarrier.try_wait.parity.acquire.cta.shared::cta.b64 P1, [%0], %1, 0x989680;\n\t" \
            "@P1 bra.uni WD_%=;\n\t"                                              \
            "bra.uni WL_%=;\n\t"                                                  \
            "WD_%=:\n\t}" :: "r"(_m), "r"(_p) : "memory");                        \
    }                                                                             \
} while (0)

#define CP_ASYNC16(dst, src) \
    asm volatile("cp.async.cg.shared.global [%0], [%1], 16;" \
                 :: "r"((uint32_t)(dst)), "l"(src) : "memory")
#define CP_COMMIT() asm volatile("cp.async.commit_group;" ::: "memory")
#define CP_WAIT0()  asm volatile("cp.async.wait_group 0;" ::: "memory")
#define CP_WAIT1()  asm volatile("cp.async.wait_group 1;" ::: "memory")

// SS form: A from SMEM desc
__device__ __forceinline__ void mma_f16_ss(uint32_t d, uint64_t a, uint64_t b,
                                           uint32_t idesc, uint32_t en) {
    asm volatile(
        "{\n\t.reg .pred p;\n\tsetp.ne.u32 p, %4, 0;\n\t"
        "tcgen05.mma.cta_group::1.kind::f16 [%0], %1, %2, %3, {%5,%5,%5,%5}, p;\n\t}"
        :: "r"(d), "l"(a), "l"(b), "r"(idesc), "r"(en), "r"(0u) : "memory");
}
// TS form: A from TMEM
__device__ __forceinline__ void mma_f16_ts(uint32_t d, uint32_t a, uint64_t b,
                                           uint32_t idesc, uint32_t en) {
    asm volatile(
        "{\n\t.reg .pred p;\n\tsetp.ne.u32 p, %4, 0;\n\t"
        "tcgen05.mma.cta_group::1.kind::f16 [%0], [%1], %2, %3, {%5,%5,%5,%5}, p;\n\t}"
        :: "r"(d), "r"(a), "l"(b), "r"(idesc), "r"(en), "r"(0u) : "memory");
}

#define TC_LD_X32(r, addr) \
    asm volatile( \
        "tcgen05.ld.sync.aligned.32x32b.x32.b32 " \
        "{%0, %1, %2, %3, %4, %5, %6, %7, " \
        " %8, %9, %10, %11, %12, %13, %14, %15, " \
        " %16, %17, %18, %19, %20, %21, %22, %23, " \
        " %24, %25, %26, %27, %28, %29, %30, %31}, [%32];" \
        : "=r"((r)[0]),  "=r"((r)[1]),  "=r"((r)[2]),  "=r"((r)[3]), \
          "=r"((r)[4]),  "=r"((r)[5]),  "=r"((r)[6]),  "=r"((r)[7]), \
          "=r"((r)[8]),  "=r"((r)[9]),  "=r"((r)[10]), "=r"((r)[11]), \
          "=r"((r)[12]), "=r"((r)[13]), "=r"((r)[14]), "=r"((r)[15]), \
          "=r"((r)[16]), "=r"((r)[17]), "=r"((r)[18]), "=r"((r)[19]), \
          "=r"((r)[20]), "=r"((r)[21]), "=r"((r)[22]), "=r"((r)[23]), \
          "=r"((r)[24]), "=r"((r)[25]), "=r"((r)[26]), "=r"((r)[27]), \
          "=r"((r)[28]), "=r"((r)[29]), "=r"((r)[30]), "=r"((r)[31]) \
        : "r"(addr))

#define TC_ST_X16(addr, r) \
    asm volatile( \
        "tcgen05.st.sync.aligned.32x32b.x16.b32 [%0], " \
        "{%1, %2, %3, %4, %5, %6, %7, %8, " \
        " %9, %10, %11, %12, %13, %14, %15, %16};" \
        :: "r"(addr), \
           "r"((r)[0]),  "r"((r)[1]),  "r"((r)[2]),  "r"((r)[3]), \
           "r"((r)[4]),  "r"((r)[5]),  "r"((r)[6]),  "r"((r)[7]), \
           "r"((r)[8]),  "r"((r)[9]),  "r"((r)[10]), "r"((r)[11]), \
           "r"((r)[12]), "r"((r)[13]), "r"((r)[14]), "r"((r)[15]) \
        : "memory")
#endif  // USE_TCGEN05

__device__ __forceinline__ void bf16_split(float v, __nv_bfloat16& h, __nv_bfloat16& l) {
    h = __float2bfloat16(v);
    l = __float2bfloat16(v - __bfloat162float(h));
}

// ---------------------------------------------------------------------------
// Conversion kernels
// ---------------------------------------------------------------------------
__global__ void split_kernel(const float* __restrict__ src)
{
    int i = blockIdx.x * blockDim.x + threadIdx.x;     // one float4 per thread
    float4 v = ((const float4*)src)[i];
    __nv_bfloat16 h0, h1, h2, h3, l0, l1, l2, l3;
    bf16_split(v.x, h0, l0); bf16_split(v.y, h1, l1);
    bf16_split(v.z, h2, l2); bf16_split(v.w, h3, l3);
    ((__nv_bfloat162*)g_xhi)[2 * i + 0] = __halves2bfloat162(h0, h1);
    ((__nv_bfloat162*)g_xhi)[2 * i + 1] = __halves2bfloat162(h2, h3);
    ((__nv_bfloat162*)g_xlo)[2 * i + 0] = __halves2bfloat162(l0, l1);
    ((__nv_bfloat162*)g_xlo)[2 * i + 1] = __halves2bfloat162(l2, l3);
}

// All 4 weights: W[K,N] fp32 -> W^T[N,K] bf16 hi/lo. grid (32,32,4), block (32,8).
__global__ void transpose_split_kernel(const float* __restrict__ wq,
                                       const float* __restrict__ wk,
                                       const float* __restrict__ wv,
                                       const float* __restrict__ wo)
{
    __shared__ float tile[32][33];
    int z = blockIdx.z;
    const float* W = (z == 0) ? wq : (z == 1) ? wk : (z == 2) ? wv : wo;
    __nv_bfloat16* Thi = g_wthi[z];
    __nv_bfloat16* Tlo = g_wtlo[z];
    int tx = threadIdx.x, ty = threadIdx.y;
    #pragma unroll
    for (int i = 0; i < 4; ++i)
        tile[ty + i * 8][tx] = W[(size_t)(blockIdx.y * 32 + ty + i * 8) * EMB + blockIdx.x * 32 + tx];
    __syncthreads();
    #pragma unroll
    for (int i = 0; i < 4; ++i) {
        float v = tile[tx][ty + i * 8];
        __nv_bfloat16 h, l;
        bf16_split(v, h, l);
        size_t off = (size_t)(blockIdx.x * 32 + ty + i * 8) * EMB + blockIdx.y * 32 + tx;
        Thi[off] = h;
        Tlo[off] = l;
    }
}

// ---------------------------------------------------------------------------
// GEMM tile body: C[128,128] = A @ W. 128 threads, KC=32 column-half ping-pong,
// 64 KB SMEM -> 3 CTAs/SM. outmode 0: fp32. 1: bf16 hi/lo. 2: bf16 hi/lo V^T.
// ---------------------------------------------------------------------------
#if USE_TCGEN05

__device__ __forceinline__ void gemm_body(
    const __nv_bfloat16* __restrict__ Ahi, const __nv_bfloat16* __restrict__ Alo,
    const __nv_bfloat16* __restrict__ Bhi, const __nv_bfloat16* __restrict__ Blo,
    float* __restrict__ Cf, __nv_bfloat16* __restrict__ Chi, __nv_bfloat16* __restrict__ Clo,
    int outmode, int row0, int col0)
{
    extern __shared__ char smem[];
    const uint32_t sb = smem_u32(smem);
    const uint32_t tb = (sb + 1023) & ~1023u;
    const uint32_t ctl = tb + GEMM_TILES;
    const int tid = threadIdx.x, wid = tid >> 5, lid = tid & 31;

    if (wid == 0) { TC_ALLOC(ctl, 128); TC_RELINQ(); }
    if (tid == 0) { MBAR_INIT(ctl + 8, 1); MBAR_INIT(ctl + 16, 1); }
    __syncthreads();
    uint32_t tmem;
    asm volatile("ld.shared.b32 %0, [%1];" : "=r"(tmem) : "r"(ctl));

    const uint32_t idesc = (1u << 4) | (1u << 7) | (1u << 10) | (16u << 17) | (8u << 24);

    // KC=32 chunk -> byte-column half (0-63 or 64-127) of each operand tile.
    auto load_chunk = [&](int kc) {
        const int half = kc & 1;
        const int k0 = kc * 32;
        #pragma unroll
        for (int i = 0; i < 4; ++i) {
            int idx = i * 128 + tid;
            int r = idx >> 2, u = idx & 3;       // r 0..127 row, u 16B unit
            uint32_t dst = SMEM_SWZ128((uint32_t)(r * 128 + half * 64 + u * 16));
            size_t aoff = (size_t)(row0 + r) * EMB + k0 + u * 8;
            size_t boff = (size_t)(col0 + r) * EMB + k0 + u * 8;
            CP_ASYNC16(tb + dst,              Ahi + aoff);
            CP_ASYNC16(tb + G_TILE + dst,     Alo + aoff);
            CP_ASYNC16(tb + 2 * G_TILE + dst, Bhi + boff);
            CP_ASYNC16(tb + 3 * G_TILE + dst, Blo + boff);
        }
    };

    load_chunk(0); CP_COMMIT();
    load_chunk(1); CP_COMMIT();

    int ph0 = 0, ph1 = 0;
    #pragma unroll 1
    for (int kc = 0; kc < 32; ++kc) {
        const int p = kc & 1;
        if (kc >= 1) {
            const int q = (kc - 1) & 1;          // MMA(kc-1) used half q; wait then refill
            if (q == 0) { MBAR_WAIT(ctl + 8,  ph0); ph0 ^= 1; }
            else        { MBAR_WAIT(ctl + 16, ph1); ph1 ^= 1; }
            if (kc + 1 < 32) { load_chunk(kc + 1); CP_COMMIT(); }
        }
        if (kc + 1 < 32) CP_WAIT1(); else CP_WAIT0();
        __syncthreads();
        FENCE_ASYNC();

        if (wid == 0 && elect_one()) {
            TC_FENCE_AFTER();
            uint64_t ahd = MAKE_DESC(tb);
            uint64_t ald = MAKE_DESC(tb + G_TILE);
            uint64_t bhd = MAKE_DESC(tb + 2 * G_TILE);
            uint64_t bld = MAKE_DESC(tb + 3 * G_TILE);
            #pragma unroll
            for (int s = 0; s < 2; ++s) {
                uint64_t off = (uint64_t)(p * 4 + s * 2);
                mma_f16_ss(tmem, ahd + off, bhd + off, idesc, (kc > 0 || s > 0) ? 1u : 0u);
            }
            #pragma unroll
            for (int s = 0; s < 2; ++s) {
                uint64_t off = (uint64_t)(p * 4 + s * 2);
                mma_f16_ss(tmem, ahd + off, bld + off, idesc, 1u);
            }
            #pragma unroll
            for (int s = 0; s < 2; ++s) {
                uint64_t off = (uint64_t)(p * 4 + s * 2);
                mma_f16_ss(tmem, ald + off, bhd + off, idesc, 1u);
            }
            TC_COMMIT(p == 0 ? ctl + 8 : ctl + 16);
        }
    }

    // Drain: chunk31's commit (parity 1) is the only outstanding one
    MBAR_WAIT(ctl + 16, ph1);
    TC_FENCE_AFTER();

    const int brow = row0 >> 11;
    float* stg = (float*)(smem + (tb - sb));

    #pragma unroll 1
    for (int cb = 0; cb < 128; cb += 32) {
        uint32_t d[32];
        TC_LD_X32(d, tmem + cb + ((uint32_t)(wid & 3) << 21));
        TC_WAIT_LD();
        if (outmode == 0) {
            float* crow = Cf + (size_t)(row0 + wid * 32 + lid) * EMB + col0 + cb;
            #pragma unroll
            for (int j = 0; j < 32; j += 4) {
                float4 v = make_float4(__uint_as_float(d[j]), __uint_as_float(d[j + 1]),
                                       __uint_as_float(d[j + 2]), __uint_as_float(d[j + 3]));
                *(float4*)(crow + j) = v;
            }
        } else if (outmode == 1) {
            size_t rowoff = (size_t)(row0 + wid * 32 + lid) * EMB + col0 + cb;
            #pragma unroll
            for (int j = 0; j < 32; j += 2) {
                float v0 = __uint_as_float(d[j]), v1 = __uint_as_float(d[j + 1]);
                __nv_bfloat16 h0, h1, l0, l1;
                bf16_split(v0, h0, l0); bf16_split(v1, h1, l1);
                *(__nv_bfloat162*)(Chi + rowoff + j) = __halves2bfloat162(h0, h1);
                *(__nv_bfloat162*)(Clo + rowoff + j) = __halves2bfloat162(l0, l1);
            }
        } else {
            // outmode 2: transpose via SMEM staging. stg index: j*132 + s + (s>>5)
            __syncthreads();
            int r = wid * 32 + lid;
            #pragma unroll
            for (int j = 0; j < 32; ++j)
                stg[j * 132 + r + (r >> 5)] = __uint_as_float(d[j]);
            __syncthreads();
            int j = tid >> 2;
            int s0 = (tid & 3) * 32;
            const float* src = stg + j * 132 + s0 + (s0 >> 5);
            int e = col0 + cb + j;
            size_t dstb = ((size_t)(brow * 1024 + e)) * 2048 + (row0 & 2047) + s0;
            #pragma unroll
            for (int m = 0; m < 32; m += 2) {
                float v0 = src[m], v1 = src[m + 1];
                __nv_bfloat16 h0, h1, l0, l1;
                bf16_split(v0, h0, l0); bf16_split(v1, h1, l1);
                *(__nv_bfloat162*)(Chi + dstb + m) = __halves2bfloat162(h0, h1);
                *(__nv_bfloat162*)(Clo + dstb + m) = __halves2bfloat162(l0, l1);
            }
        }
    }
    TC_FENCE_BEFORE();
    __syncthreads();
    if (tid == 0) { MBAR_INVAL(ctl + 8); MBAR_INVAL(ctl + 16); }
    __syncthreads();
    if (wid == 0) TC_DEALLOC(tmem, 128);
}

#else  // !USE_TCGEN05 — correct SIMT fallback

__device__ __forceinline__ void gemm_body(
    const __nv_bfloat16* __restrict__ Ahi, const __nv_bfloat16* __restrict__ Alo,
    const __nv_bfloat16* __restrict__ Bhi, const __nv_bfloat16* __restrict__ Blo,
    float* __restrict__ Cf, __nv_bfloat16* __restrict__ Chi, __nv_bfloat16* __restrict__ Clo,
    int outmode, int row0, int col0)
{
    extern __shared__ char smem[];
    float* arow = (float*)smem;
    const int tid = threadIdx.x;
    const int brow = row0 >> 11;
    const __nv_bfloat16* bh = Bhi + (size_t)(col0 + tid) * EMB;
    const __nv_bfloat16* bl = Blo + (size_t)(col0 + tid) * EMB;
    for (int r = 0; r < 128; ++r) {
        __syncthreads();
        for (int i = tid; i < EMB; i += 128) {
            size_t off = (size_t)(row0 + r) * EMB + i;
            arow[i] = __bfloat162float(Ahi[off]) + __bfloat162float(Alo[off]);
        }
        __syncthreads();
        float acc = 0.f;
        for (int k = 0; k < EMB; ++k)
            acc = fmaf(arow[k], __bfloat162float(bh[k]) + __bfloat162float(bl[k]), acc);
        if (outmode == 0) {
            Cf[(size_t)(row0 + r) * EMB + col0 + tid] = acc;
        } else if (outmode == 1) {
            __nv_bfloat16 h, l; bf16_split(acc, h, l);
            size_t o = (size_t)(row0 + r) * EMB + col0 + tid;
            Chi[o] = h; Clo[o] = l;
        } else {
            __nv_bfloat16 h, l; bf16_split(acc, h, l);
            size_t o = ((size_t)(brow * 1024 + col0 + tid)) * 2048 + (row0 & 2047) + r;
            Chi[o] = h; Clo[o] = l;
        }
    }
}
#endif  // USE_TCGEN05

// grid (32, 8, 3): z = 0/1/2 -> Q/K/V. V written transposed (outmode 2).
__global__ __launch_bounds__(128, 3) void gemm_qkv_kernel()
{
    int z = blockIdx.z;
    __nv_bfloat16* hi = (z == 0) ? g_qhi : (z == 1) ? g_khi : g_vthi;
    __nv_bfloat16* lo = (z == 0) ? g_qlo : (z == 1) ? g_klo : g_vtlo;
    gemm_body(g_xhi, g_xlo, g_wthi[z], g_wtlo[z], nullptr, hi, lo, (z == 2) ? 2 : 1,
              blockIdx.x * 128, blockIdx.y * 128);
}

// grid (32, 8): out = ctx @ Wo (fp32 output)
__global__ __launch_bounds__(128, 3) void gemm_out_kernel(float* __restrict__ out)
{
    gemm_body(g_chi, g_clo, g_wthi[3], g_wtlo[3], out, nullptr, nullptr, 0,
              blockIdx.x * 128, blockIdx.y * 128);
}

// ---------------------------------------------------------------------------
// Tensorized causal attention, 64-key blocks, 2 CTAs/SM (unchanged from R11).
// TMEM (alloc 256): S0 0-63 | S1 64-127 | Phi 128-159 | Plo 160-191 | O 192-255.
// ---------------------------------------------------------------------------
#if USE_TCGEN05

__global__ __launch_bounds__(256, 2) void attn_tc_kernel()
{
    extern __shared__ char smem[];
    const uint32_t sb = smem_u32(smem);
    const uint32_t tb = (sb + 1023) & ~1023u;
    const uint32_t ctl = tb + AT_TILES;

    const int tid = threadIdx.x, wid = tid >> 5, lane = tid & 31;
    const int sp = wid & 3;              // TMEM subpartition
    const int ch = wid >> 2;             // column half of 64 (0/1)
    const int bid = blockIdx.x;
    const int qtile = 15 - (bid >> 5);   // descending work
    const int hb = bid & 31;
    const int h = hb & 15, b = hb >> 4;
    const int row = sp * 32 + lane;
    const int qr = qtile * 128 + row;
    const uint32_t rbase = (uint32_t)sp << 21;

    const uint32_t QH = tb, QL = tb + 16384;

    if (wid == 0) { TC_ALLOC(ctl, 256); TC_RELINQ(); }
    if (tid == 0) { MBAR_INIT(ctl + 8, 1); MBAR_INIT(ctl + 16, 1); MBAR_INIT(ctl + 24, 1); }
    __syncthreads();
    uint32_t tmem;
    asm volatile("ld.shared.b32 %0, [%1];" : "=r"(tmem) : "r"(ctl));

    const uint32_t IDESC = (1u << 4) | (1u << 7) | (1u << 10) | (8u << 17) | (8u << 24);
    const uint32_t PH_COL = 128, PL_COL = 160, O_COL = 192;

    const size_t khead = (size_t)(b * SEQ) * EMB + h * HDIM;
    const size_t vhead = (size_t)((b * HEADS + h) * HDIM) * SEQ;
    const int ntk = 2 * qtile + 2;       // 64-key blocks

    auto load_k = [&](int kb, uint32_t ks) {
        const size_t base = khead + (size_t)(kb * 64) * EMB;
        #pragma unroll
        for (int i = 0; i < 2; ++i) {
            int idx = i * 256 + tid;
            int r = idx >> 3, u = idx & 7;
            uint32_t dst = SMEM_SWZ128((uint32_t)(r * 128 + u * 16));
            size_t off = base + (size_t)r * EMB + u * 8;
            CP_ASYNC16(ks + dst,        g_khi + off);
            CP_ASYNC16(ks + 8192 + dst, g_klo + off);
        }
    };
    auto load_v = [&](int kb, uint32_t vs) {
        const size_t base = vhead + kb * 64;
        #pragma unroll
        for (int i = 0; i < 2; ++i) {
            int idx = i * 256 + tid;
            int r = idx >> 3, u = idx & 7;
            uint32_t dst = SMEM_SWZ128((uint32_t)(r * 128 + u * 16));
            size_t off = base + (size_t)r * SEQ + u * 8;
            CP_ASYNC16(vs + dst,        g_vthi + off);
            CP_ASYNC16(vs + 8192 + dst, g_vtlo + off);
        }
    };

    auto issue_smma = [&](uint32_t d, uint32_t ks) {
        uint64_t qhd = MAKE_DESC(QH), qld = MAKE_DESC(QL);
        uint64_t khd = MAKE_DESC(ks), kld = MAKE_DESC(ks + 8192);
        #pragma unroll
        for (int s = 0; s < 4; ++s)
            mma_f16_ss(d, qhd + s * 2, khd + s * 2, IDESC, s > 0 ? 1u : 0u);
        #pragma unroll
        for (int s = 0; s < 4; ++s)
            mma_f16_ss(d, qhd + s * 2, kld + s * 2, IDESC, 1u);
        #pragma unroll
        for (int s = 0; s < 4; ++s)
            mma_f16_ss(d, qld + s * 2, khd + s * 2, IDESC, 1u);
    };

    // ---- Preamble: Q + K(0) + V(0) [group1], K(1) [group2] ----
    {
        const __nv_bfloat16* qh = g_qhi + khead + (size_t)(qtile * 128) * EMB;
        const __nv_bfloat16* ql = g_qlo + khead + (size_t)(qtile * 128) * EMB;
        #pragma unroll
        for (int i = 0; i < 4; ++i) {
            int idx = i * 256 + tid;
            int r = idx >> 3, u = idx & 7;
            uint32_t dst = SMEM_SWZ128((uint32_t)(r * 128 + u * 16));
            size_t off = (size_t)r * EMB + u * 8;
            CP_ASYNC16(QH + dst, qh + off);
            CP_ASYNC16(QL + dst, ql + off);
        }
        load_k(0, tb + 32768);
        load_v(0, tb + 65536);
        CP_COMMIT();
        load_k(1, tb + 32768 + 16384);
        CP_COMMIT();
        CP_WAIT1();
        __syncthreads();
        FENCE_ASYNC();
    }

    if (wid == 0 && elect_one()) {
        TC_FENCE_AFTER();
        issue_smma(tmem, tb + 32768);    // S(0) -> S-buf 0
        TC_COMMIT(ctl + 8);
    }

    float lpart = 0.f;
    int ph_s0 = 0, ph_s1 = 0, ph_o = 0;

    #pragma unroll 1
    for (int kb = 0; kb < ntk; ++kb) {
        CP_WAIT0();
        __syncthreads();
        FENCE_ASYNC();
        if (kb + 1 < ntk && wid == 0 && elect_one()) {
            TC_FENCE_AFTER();
            issue_smma(tmem + ((kb + 1) & 1) * 64, tb + 32768 + ((kb + 1) & 1) * 16384);
            TC_COMMIT((kb + 1) & 1 ? ctl + 24 : ctl + 8);
        }

        if (kb & 1) { MBAR_WAIT(ctl + 24, ph_s1); ph_s1 ^= 1; }
        else        { MBAR_WAIT(ctl + 8,  ph_s0); ph_s0 ^= 1; }
        TC_FENCE_AFTER();

        uint32_t sreg[32];
        TC_LD_X32(sreg, tmem + (kb & 1) * 64 + ch * 32 + rbase);
        TC_WAIT_LD();

        if (kb + 2 < ntk) { load_k(kb + 2, tb + 32768 + (kb & 1) * 16384); CP_COMMIT(); }

        const int jg0 = kb * 64 + ch * 32;
        const bool diag = (kb >= ntk - 2);
        uint32_t phi[16], plo[16];
        float lsum = 0.f;
        #pragma unroll
        for (int c = 0; c < 16; ++c) {
            float p0 = exp2f(fmaf(__uint_as_float(sreg[2 * c]),     0.1803368801f, -17.3123405f));
            float p1 = exp2f(fmaf(__uint_as_float(sreg[2 * c + 1]), 0.1803368801f, -17.3123405f));
            if (diag) {
                if (jg0 + 2 * c     > qr) p0 = 0.f;
                if (jg0 + 2 * c + 1 > qr) p1 = 0.f;
            }
            lsum += p0 + p1;
            uint32_t u0 = __float_as_uint(p0), u1 = __float_as_uint(p1);
            float h0 = __uint_as_float(u0 & 0xffff0000u);
            float h1 = __uint_as_float(u1 & 0xffff0000u);
            phi[c] = __byte_perm(u0, u1, 0x7632);
            __nv_bfloat162 lp = __floats2bfloat162_rn(p0 - h0, p1 - h1);
            plo[c] = *reinterpret_cast<uint32_t*>(&lp);
        }
        lpart += lsum;

        if (kb > 0) { MBAR_WAIT(ctl + 16, ph_o); ph_o ^= 1; }
        if (kb + 1 < ntk) { load_v(kb + 1, tb + 65536 + ((kb + 1) & 1) * 16384); CP_COMMIT(); }

        TC_ST_X16(tmem + PH_COL + ch * 16 + rbase, phi);
        TC_ST_X16(tmem + PL_COL + ch * 16 + rbase, plo);
        TC_WAIT_ST();
        TC_FENCE_BEFORE();
        __syncthreads();

        if (wid == 0 && elect_one()) {
            TC_FENCE_AFTER();
            const uint32_t vsb = tb + 65536 + (kb & 1) * 16384;
            uint64_t vhd = MAKE_DESC(vsb);
            uint64_t vld = MAKE_DESC(vsb + 8192);
            #pragma unroll
            for (int s = 0; s < 4; ++s)
                mma_f16_ts(tmem + O_COL, tmem + PH_COL + s * 8, vhd + s * 2, IDESC,
                           (kb > 0 || s > 0) ? 1u : 0u);
            #pragma unroll
            for (int s = 0; s < 4; ++s)
                mma_f16_ts(tmem + O_COL, tmem + PH_COL + s * 8, vld + s * 2, IDESC, 1u);
            #pragma unroll
            for (int s = 0; s < 4; ++s)
                mma_f16_ts(tmem + O_COL, tmem + PL_COL + s * 8, vhd + s * 2, IDESC, 1u);
            TC_COMMIT(ctl + 16);
        }
    }

    MBAR_WAIT(ctl + 16, ph_o);
    TC_FENCE_AFTER();

    float* lred = (float*)(smem + (tb - sb));
    lred[ch * 128 + row] = lpart;
    __syncthreads();
    const float inv = 1.f / (lred[row] + lred[128 + row]);

    uint32_t oreg[32];
    TC_LD_X32(oreg, tmem + O_COL + ch * 32 + rbase);
    TC_WAIT_LD();
    {
        size_t obase = (size_t)(b * SEQ + qr) * EMB + h * HDIM + ch * 32;
        #pragma unroll
        for (int j = 0; j < 32; j += 2) {
            float v0 = __uint_as_float(oreg[j]) * inv;
            float v1 = __uint_as_float(oreg[j + 1]) * inv;
            __nv_bfloat16 h0, h1, l0, l1;
            bf16_split(v0, h0, l0); bf16_split(v1, h1, l1);
            *(__nv_bfloat162*)(g_chi + obase + j) = __halves2bfloat162(h0, h1);
            *(__nv_bfloat162*)(g_clo + obase + j) = __halves2bfloat162(l0, l1);
        }
    }
    TC_FENCE_BEFORE();
    __syncthreads();
    if (tid == 0) { MBAR_INVAL(ctl + 8); MBAR_INVAL(ctl + 16); MBAR_INVAL(ctl + 24); }
    __syncthreads();
    if (wid == 0) TC_DEALLOC(tmem, 256);
}

#else  // fallback SIMT attention (compute_103 pass only)

__global__ __launch_bounds__(256, 2) void attn_tc_kernel()
{
    const int bid = blockIdx.x;
    const int qtile = 15 - (bid >> 5);
    const int hb = bid & 31;
    const int h = hb & 15, b = hb >> 4;
    const int t = threadIdx.x;
    const int qr = qtile * 128 + (t & 127);
    const size_t headbase = (size_t)b * SEQ * EMB + (size_t)h * HDIM;
    const size_t vthead = (size_t)((b * HEADS + h) * HDIM) * SEQ;

    __shared__ float Ks[128 * HDIM];
    __shared__ float Vs[128 * HDIM];

    float q[HDIM], acc[HDIM];
    if (t < 128) {
        for (int d = 0; d < HDIM; ++d) {
            size_t off = headbase + (size_t)qr * EMB + d;
            q[d] = __bfloat162float(g_qhi[off]) + __bfloat162float(g_qlo[off]);
            acc[d] = 0.f;
        }
    }
    float l = 0.f;
    for (int kt = 0; kt <= qtile; ++kt) {
        __syncthreads();
        for (int i = t; i < 128 * HDIM; i += 256) {
            int r = i / HDIM, d = i % HDIM;
            size_t koff = headbase + (size_t)(kt * 128 + r) * EMB + d;
            Ks[i] = __bfloat162float(g_khi[koff]) + __bfloat162float(g_klo[koff]);
            size_t voff = vthead + (size_t)d * SEQ + kt * 128 + r;
            Vs[i] = __bfloat162float(g_vthi[voff]) + __bfloat162float(g_vtlo[voff]);
        }
        __syncthreads();
        if (t < 128) {
            int jmax = (kt == qtile) ? (qr - kt * 128) : 127;
            for (int j = 0; j <= jmax; ++j) {
                float s = 0.f;
                for (int d = 0; d < HDIM; ++d) s = fmaf(q[d], Ks[j * HDIM + d], s);
                float p = __expf(fmaf(s, 0.125f, -12.f));
                l += p;
                for (int d = 0; d < HDIM; ++d) acc[d] = fmaf(p, Vs[j * HDIM + d], acc[d]);
            }
        }
    }
    if (t < 128) {
        float inv = 1.f / l;
        for (int d = 0; d < HDIM; ++d) {
            __nv_bfloat16 hh, ll;
            bf16_split(acc[d] * inv, hh, ll);
            size_t off = headbase + (size_t)qr * EMB + d;
            g_chi[off] = hh;
            g_clo[off] = ll;
        }
    }
}
#endif

// ---------------------------------------------------------------------------
extern "C" void kernel_launch(void* const* d_in, const int* in_sizes, int n_in,
                              void* d_out, int out_size)
{
    const float* x  = (const float*)d_in[0];
    const float* wq = (const float*)d_in[1];
    const float* wk = (const float*)d_in[2];
    const float* wv = (const float*)d_in[3];
    const float* wo = (const float*)d_in[4];
    float* out = (float*)d_out;

    cudaFuncSetAttribute(gemm_qkv_kernel, cudaFuncAttributeMaxDynamicSharedMemorySize, SMEM_DYN);
    cudaFuncSetAttribute(gemm_out_kernel, cudaFuncAttributeMaxDynamicSharedMemorySize, SMEM_DYN);
    cudaFuncSetAttribute(attn_tc_kernel,  cudaFuncAttributeMaxDynamicSharedMemorySize, AT_SMEM);

    // 1) fp32 -> bf16 hi/lo splits (x) + all 4 weight transposes
    split_kernel<<<(MTOT * EMB / 4) / 256, 256>>>(x);
    transpose_split_kernel<<<dim3(32, 32, 4), dim3(32, 8)>>>(wq, wk, wv, wo);

    // 2) QKV projections (KC=32 ping-pong, 3 CTAs/SM); V epilogue writes V^T
    gemm_qkv_kernel<<<dim3(32, 8, 3), 128, SMEM_DYN>>>();

    // 3) Tensorized causal attention, 64-key blocks, 2 CTAs/SM
    attn_tc_kernel<<<512, 256, AT_SMEM>>>();

    // 4) Output projection (fp32 out)
    gemm_out_kernel<<<dim3(32, 8), 128, SMEM_DYN>>>(out);
}

// round 14
// speedup vs baseline: 1.0038x; 1.0038x over previous
#include <cuda_runtime.h>
#include <cuda_bf16.h>
#include <cstdint>

// Problem constants
#define BATCH 2
#define SEQ   2048
#define EMB   1024
#define HEADS 16
#define HDIM  64
#define MTOT  (BATCH*SEQ)   // 4096

#if defined(__CUDA_ARCH_SPECIFIC__) || defined(__CUDA_ARCH_FEAT_SM103_ALL) || \
    defined(__CUDA_ARCH_FEAT_SM100_ALL) || defined(__CUDA_ARCH_FAMILY_SPECIFIC__)
#define USE_TCGEN05 1
#else
#define USE_TCGEN05 0
#endif

// Scratch (allocation-free rule: __device__ globals)
__device__ __nv_bfloat16 g_xhi[MTOT * EMB];
__device__ __nv_bfloat16 g_xlo[MTOT * EMB];
__device__ __nv_bfloat16 g_qhi[MTOT * EMB];
__device__ __nv_bfloat16 g_qlo[MTOT * EMB];
__device__ __nv_bfloat16 g_khi[MTOT * EMB];
__device__ __nv_bfloat16 g_klo[MTOT * EMB];
__device__ __nv_bfloat16 g_vthi[MTOT * EMB];  // [b][h][d][s] (written by V GEMM epilogue)
__device__ __nv_bfloat16 g_vtlo[MTOT * EMB];
__device__ __nv_bfloat16 g_chi[MTOT * EMB];   // attention output (ctx) hi/lo
__device__ __nv_bfloat16 g_clo[MTOT * EMB];
__device__ __nv_bfloat16 g_wthi[4][EMB * EMB];   // W^T hi (q,k,v,o)
__device__ __nv_bfloat16 g_wtlo[4][EMB * EMB];

// GEMM: 128x128 tile, KC=32 chunks ping-pong between byte-column halves of one
// SW128 tile per operand. SMEM: Ahi 16K | Alo 16K | Bhi 16K | Blo 16K = 64K.
#define G_TILE   16384
#define GEMM_TILES 65536
#define SMEM_DYN (1024 + GEMM_TILES + 64)

// Attention SMEM: Q hi/lo 32K + K 2-ring (16K/stage) + V 2-ring (16K/stage)
#define AT_TILES 98304
#define AT_SMEM  (1024 + AT_TILES + 64)

#if USE_TCGEN05
// ---------------------------------------------------------------------------
// PTX helpers (sm_103a only)
// ---------------------------------------------------------------------------
__device__ __forceinline__ uint32_t smem_u32(const void* p) {
    uint32_t a;
    asm("{ .reg .u64 t; cvta.to.shared.u64 t, %1; cvt.u32.u64 %0, t; }" : "=r"(a) : "l"(p));
    return a;
}
__device__ __forceinline__ uint32_t elect_one() {
    uint32_t pred;
    asm volatile("{\n\t.reg .pred p;\n\telect.sync _|p, 0xFFFFFFFF;\n\t"
                 "selp.b32 %0, 1, 0, p;\n\t}" : "=r"(pred));
    return pred;
}
#define SMEM_SWZ128(off) ((off) ^ (((off) >> 3) & 0x70))

static constexpr uint64_t DESC_BASE_SW128 =
    (uint64_t(2) << 61) | (uint64_t(1) << 46) | (uint64_t(64) << 32) | (uint64_t(1) << 16);
#define MAKE_DESC(addr) (DESC_BASE_SW128 | ((uint64_t)((addr) >> 4) & 0x3FFF))

#define TC_ALLOC(sdst, n) \
    asm volatile("tcgen05.alloc.cta_group::1.sync.aligned.shared::cta.b32 [%0], %1;" \
                 :: "r"((uint32_t)(sdst)), "r"((uint32_t)(n)) : "memory")
#define TC_DEALLOC(t, n) \
    asm volatile("tcgen05.dealloc.cta_group::1.sync.aligned.b32 %0, %1;" :: "r"(t), "r"(n))
#define TC_RELINQ() \
    asm volatile("tcgen05.relinquish_alloc_permit.cta_group::1.sync.aligned;")
#define TC_COMMIT(mb) \
    asm volatile("tcgen05.commit.cta_group::1.mbarrier::arrive::one.shared::cluster.b64 [%0];" \
                 :: "r"((uint32_t)(mb)) : "memory")
#define TC_FENCE_AFTER()  asm volatile("tcgen05.fence::after_thread_sync;" ::: "memory")
#define TC_FENCE_BEFORE() asm volatile("tcgen05.fence::before_thread_sync;" ::: "memory")
#define TC_WAIT_LD()      asm volatile("tcgen05.wait::ld.sync.aligned;" ::: "memory")
#define TC_WAIT_ST()      asm volatile("tcgen05.wait::st.sync.aligned;" ::: "memory")
#define FENCE_ASYNC()     asm volatile("fence.proxy.async.shared::cta;" ::: "memory")
#define MBAR_INIT(mb, c) \
    asm volatile("mbarrier.init.shared.b64 [%0], %1;" :: "r"((uint32_t)(mb)), "r"((uint32_t)(c)) : "memory")
#define MBAR_INVAL(mb) \
    asm volatile("mbarrier.inval.shared.b64 [%0];" :: "r"((uint32_t)(mb)) : "memory")

#define MBAR_WAIT(mb, ph) do {                                                    \
    uint32_t _m = (uint32_t)(mb), _p = (uint32_t)(ph), _d;                        \
    asm volatile("{\n\t.reg .pred p;\n\t"                                         \
        "mbarrier.try_wait.parity.acquire.cta.shared::cta.b64 p, [%1], %2;\n\t"   \
        "selp.b32 %0, 1, 0, p;\n\t}" : "=r"(_d) : "r"(_m), "r"(_p) : "memory");   \
    if (!_d) {                                                                    \
        asm volatile("{\n\t.reg .pred P1;\n\t"                                    \
            "WL_%=:\n\t"                                                          \
            "mbarrier.try_wait.parity.acquire.cta.shared::cta.b64 P1, [%0], %1, 0x989680;\n\t" \
            "@P1 bra.uni WD_%=;\n\t"                                              \
            "bra.uni WL_%=;\n\t"                                                  \
            "WD_%=:\n\t}" :: "r"(_m), "r"(_p) : "memory");                        \
    }                                                                             \
} while (0)

#define CP_ASYNC16(dst, src) \
    asm volatile("cp.async.cg.shared.global [%0], [%1], 16;" \
                 :: "r"((uint32_t)(dst)), "l"(src) : "memory")
#define CP_COMMIT() asm volatile("cp.async.commit_group;" ::: "memory")
#define CP_WAIT0()  asm volatile("cp.async.wait_group 0;" ::: "memory")
#define CP_WAIT1()  asm volatile("cp.async.wait_group 1;" ::: "memory")

// SS form: A from SMEM desc
__device__ __forceinline__ void mma_f16_ss(uint32_t d, uint64_t a, uint64_t b,
                                           uint32_t idesc, uint32_t en) {
    asm volatile(
        "{\n\t.reg .pred p;\n\tsetp.ne.u32 p, %4, 0;\n\t"
        "tcgen05.mma.cta_group::1.kind::f16 [%0], %1, %2, %3, {%5,%5,%5,%5}, p;\n\t}"
        :: "r"(d), "l"(a), "l"(b), "r"(idesc), "r"(en), "r"(0u) : "memory");
}
// TS form: A from TMEM
__device__ __forceinline__ void mma_f16_ts(uint32_t d, uint32_t a, uint64_t b,
                                           uint32_t idesc, uint32_t en) {
    asm volatile(
        "{\n\t.reg .pred p;\n\tsetp.ne.u32 p, %4, 0;\n\t"
        "tcgen05.mma.cta_group::1.kind::f16 [%0], [%1], %2, %3, {%5,%5,%5,%5}, p;\n\t}"
        :: "r"(d), "r"(a), "l"(b), "r"(idesc), "r"(en), "r"(0u) : "memory");
}

#define TC_LD_X32(r, addr) \
    asm volatile( \
        "tcgen05.ld.sync.aligned.32x32b.x32.b32 " \
        "{%0, %1, %2, %3, %4, %5, %6, %7, " \
        " %8, %9, %10, %11, %12, %13, %14, %15, " \
        " %16, %17, %18, %19, %20, %21, %22, %23, " \
        " %24, %25, %26, %27, %28, %29, %30, %31}, [%32];" \
        : "=r"((r)[0]),  "=r"((r)[1]),  "=r"((r)[2]),  "=r"((r)[3]), \
          "=r"((r)[4]),  "=r"((r)[5]),  "=r"((r)[6]),  "=r"((r)[7]), \
          "=r"((r)[8]),  "=r"((r)[9]),  "=r"((r)[10]), "=r"((r)[11]), \
          "=r"((r)[12]), "=r"((r)[13]), "=r"((r)[14]), "=r"((r)[15]), \
          "=r"((r)[16]), "=r"((r)[17]), "=r"((r)[18]), "=r"((r)[19]), \
          "=r"((r)[20]), "=r"((r)[21]), "=r"((r)[22]), "=r"((r)[23]), \
          "=r"((r)[24]), "=r"((r)[25]), "=r"((r)[26]), "=r"((r)[27]), \
          "=r"((r)[28]), "=r"((r)[29]), "=r"((r)[30]), "=r"((r)[31]) \
        : "r"(addr))

#define TC_ST_X16(addr, r) \
    asm volatile( \
        "tcgen05.st.sync.aligned.32x32b.x16.b32 [%0], " \
        "{%1, %2, %3, %4, %5, %6, %7, %8, " \
        " %9, %10, %11, %12, %13, %14, %15, %16};" \
        :: "r"(addr), \
           "r"((r)[0]),  "r"((r)[1]),  "r"((r)[2]),  "r"((r)[3]), \
           "r"((r)[4]),  "r"((r)[5]),  "r"((r)[6]),  "r"((r)[7]), \
           "r"((r)[8]),  "r"((r)[9]),  "r"((r)[10]), "r"((r)[11]), \
           "r"((r)[12]), "r"((r)[13]), "r"((r)[14]), "r"((r)[15]) \
        : "memory")
#endif  // USE_TCGEN05

__device__ __forceinline__ void bf16_split(float v, __nv_bfloat16& h, __nv_bfloat16& l) {
    h = __float2bfloat16(v);
    l = __float2bfloat16(v - __bfloat162float(h));
}

// ---------------------------------------------------------------------------
// Conversion kernels
// ---------------------------------------------------------------------------
__global__ void split_kernel(const float* __restrict__ src)
{
    int i = blockIdx.x * blockDim.x + threadIdx.x;     // one float4 per thread
    float4 v = ((const float4*)src)[i];
    __nv_bfloat16 h0, h1, h2, h3, l0, l1, l2, l3;
    bf16_split(v.x, h0, l0); bf16_split(v.y, h1, l1);
    bf16_split(v.z, h2, l2); bf16_split(v.w, h3, l3);
    ((__nv_bfloat162*)g_xhi)[2 * i + 0] = __halves2bfloat162(h0, h1);
    ((__nv_bfloat162*)g_xhi)[2 * i + 1] = __halves2bfloat162(h2, h3);
    ((__nv_bfloat162*)g_xlo)[2 * i + 0] = __halves2bfloat162(l0, l1);
    ((__nv_bfloat162*)g_xlo)[2 * i + 1] = __halves2bfloat162(l2, l3);
}

// All 4 weights: W[K,N] fp32 -> W^T[N,K] bf16 hi/lo. grid (32,32,4), block (32,8).
__global__ void transpose_split_kernel(const float* __restrict__ wq,
                                       const float* __restrict__ wk,
                                       const float* __restrict__ wv,
                                       const float* __restrict__ wo)
{
    __shared__ float tile[32][33];
    int z = blockIdx.z;
    const float* W = (z == 0) ? wq : (z == 1) ? wk : (z == 2) ? wv : wo;
    __nv_bfloat16* Thi = g_wthi[z];
    __nv_bfloat16* Tlo = g_wtlo[z];
    int tx = threadIdx.x, ty = threadIdx.y;
    #pragma unroll
    for (int i = 0; i < 4; ++i)
        tile[ty + i * 8][tx] = W[(size_t)(blockIdx.y * 32 + ty + i * 8) * EMB + blockIdx.x * 32 + tx];
    __syncthreads();
    #pragma unroll
    for (int i = 0; i < 4; ++i) {
        float v = tile[tx][ty + i * 8];
        __nv_bfloat16 h, l;
        bf16_split(v, h, l);
        size_t off = (size_t)(blockIdx.x * 32 + ty + i * 8) * EMB + blockIdx.y * 32 + tx;
        Thi[off] = h;
        Tlo[off] = l;
    }
}

// ---------------------------------------------------------------------------
// GEMM tile body: C[128,128] = A @ W. 128 threads, KC=32 column-half ping-pong,
// 64 KB SMEM -> 3 CTAs/SM. outmode 0: fp32. 1: bf16 hi/lo. 2: bf16 hi/lo V^T.
// ---------------------------------------------------------------------------
#if USE_TCGEN05

__device__ __forceinline__ void gemm_body(
    const __nv_bfloat16* __restrict__ Ahi, const __nv_bfloat16* __restrict__ Alo,
    const __nv_bfloat16* __restrict__ Bhi, const __nv_bfloat16* __restrict__ Blo,
    float* __restrict__ Cf, __nv_bfloat16* __restrict__ Chi, __nv_bfloat16* __restrict__ Clo,
    int outmode, int row0, int col0)
{
    extern __shared__ char smem[];
    const uint32_t sb = smem_u32(smem);
    const uint32_t tb = (sb + 1023) & ~1023u;
    const uint32_t ctl = tb + GEMM_TILES;
    const int tid = threadIdx.x, wid = tid >> 5, lid = tid & 31;

    if (wid == 0) { TC_ALLOC(ctl, 128); TC_RELINQ(); }
    if (tid == 0) { MBAR_INIT(ctl + 8, 1); MBAR_INIT(ctl + 16, 1); }
    __syncthreads();
    uint32_t tmem;
    asm volatile("ld.shared.b32 %0, [%1];" : "=r"(tmem) : "r"(ctl));

    const uint32_t idesc = (1u << 4) | (1u << 7) | (1u << 10) | (16u << 17) | (8u << 24);

    // KC=32 chunk -> byte-column half (0-63 or 64-127) of each operand tile.
    auto load_chunk = [&](int kc) {
        const int half = kc & 1;
        const int k0 = kc * 32;
        #pragma unroll
        for (int i = 0; i < 4; ++i) {
            int idx = i * 128 + tid;
            int r = idx >> 2, u = idx & 3;       // r 0..127 row, u 16B unit
            uint32_t dst = SMEM_SWZ128((uint32_t)(r * 128 + half * 64 + u * 16));
            size_t aoff = (size_t)(row0 + r) * EMB + k0 + u * 8;
            size_t boff = (size_t)(col0 + r) * EMB + k0 + u * 8;
            CP_ASYNC16(tb + dst,              Ahi + aoff);
            CP_ASYNC16(tb + G_TILE + dst,     Alo + aoff);
            CP_ASYNC16(tb + 2 * G_TILE + dst, Bhi + boff);
            CP_ASYNC16(tb + 3 * G_TILE + dst, Blo + boff);
        }
    };

    load_chunk(0); CP_COMMIT();
    load_chunk(1); CP_COMMIT();

    int ph0 = 0, ph1 = 0;
    #pragma unroll 1
    for (int kc = 0; kc < 32; ++kc) {
        const int p = kc & 1;
        if (kc >= 1) {
            const int q = (kc - 1) & 1;          // MMA(kc-1) used half q; wait then refill
            if (q == 0) { MBAR_WAIT(ctl + 8,  ph0); ph0 ^= 1; }
            else        { MBAR_WAIT(ctl + 16, ph1); ph1 ^= 1; }
            if (kc + 1 < 32) { load_chunk(kc + 1); CP_COMMIT(); }
        }
        if (kc + 1 < 32) CP_WAIT1(); else CP_WAIT0();
        __syncthreads();
        FENCE_ASYNC();

        if (wid == 0 && elect_one()) {
            TC_FENCE_AFTER();
            uint64_t ahd = MAKE_DESC(tb);
            uint64_t ald = MAKE_DESC(tb + G_TILE);
            uint64_t bhd = MAKE_DESC(tb + 2 * G_TILE);
            uint64_t bld = MAKE_DESC(tb + 3 * G_TILE);
            #pragma unroll
            for (int s = 0; s < 2; ++s) {
                uint64_t off = (uint64_t)(p * 4 + s * 2);
                mma_f16_ss(tmem, ahd + off, bhd + off, idesc, (kc > 0 || s > 0) ? 1u : 0u);
            }
            #pragma unroll
            for (int s = 0; s < 2; ++s) {
                uint64_t off = (uint64_t)(p * 4 + s * 2);
                mma_f16_ss(tmem, ahd + off, bld + off, idesc, 1u);
            }
            #pragma unroll
            for (int s = 0; s < 2; ++s) {
                uint64_t off = (uint64_t)(p * 4 + s * 2);
                mma_f16_ss(tmem, ald + off, bhd + off, idesc, 1u);
            }
            TC_COMMIT(p == 0 ? ctl + 8 : ctl + 16);
        }
    }

    // Drain: chunk31's commit (parity 1) is the only outstanding one
    MBAR_WAIT(ctl + 16, ph1);
    TC_FENCE_AFTER();

    const int brow = row0 >> 11;
    float* stg = (float*)(smem + (tb - sb));

    #pragma unroll 1
    for (int cb = 0; cb < 128; cb += 32) {
        uint32_t d[32];
        TC_LD_X32(d, tmem + cb + ((uint32_t)(wid & 3) << 21));
        TC_WAIT_LD();
        if (outmode == 0) {
            float* crow = Cf + (size_t)(row0 + wid * 32 + lid) * EMB + col0 + cb;
            #pragma unroll
            for (int j = 0; j < 32; j += 4) {
                float4 v = make_float4(__uint_as_float(d[j]), __uint_as_float(d[j + 1]),
                                       __uint_as_float(d[j + 2]), __uint_as_float(d[j + 3]));
                *(float4*)(crow + j) = v;
            }
        } else if (outmode == 1) {
            size_t rowoff = (size_t)(row0 + wid * 32 + lid) * EMB + col0 + cb;
            #pragma unroll
            for (int j = 0; j < 32; j += 2) {
                float v0 = __uint_as_float(d[j]), v1 = __uint_as_float(d[j + 1]);
                __nv_bfloat16 h0, h1, l0, l1;
                bf16_split(v0, h0, l0); bf16_split(v1, h1, l1);
                *(__nv_bfloat162*)(Chi + rowoff + j) = __halves2bfloat162(h0, h1);
                *(__nv_bfloat162*)(Clo + rowoff + j) = __halves2bfloat162(l0, l1);
            }
        } else {
            // outmode 2: transpose via SMEM staging. stg index: j*132 + s + (s>>5)
            __syncthreads();
            int r = wid * 32 + lid;
            #pragma unroll
            for (int j = 0; j < 32; ++j)
                stg[j * 132 + r + (r >> 5)] = __uint_as_float(d[j]);
            __syncthreads();
            int j = tid >> 2;
            int s0 = (tid & 3) * 32;
            const float* src = stg + j * 132 + s0 + (s0 >> 5);
            int e = col0 + cb + j;
            size_t dstb = ((size_t)(brow * 1024 + e)) * 2048 + (row0 & 2047) + s0;
            #pragma unroll
            for (int m = 0; m < 32; m += 2) {
                float v0 = src[m], v1 = src[m + 1];
                __nv_bfloat16 h0, h1, l0, l1;
                bf16_split(v0, h0, l0); bf16_split(v1, h1, l1);
                *(__nv_bfloat162*)(Chi + dstb + m) = __halves2bfloat162(h0, h1);
                *(__nv_bfloat162*)(Clo + dstb + m) = __halves2bfloat162(l0, l1);
            }
        }
    }
    TC_FENCE_BEFORE();
    __syncthreads();
    if (tid == 0) { MBAR_INVAL(ctl + 8); MBAR_INVAL(ctl + 16); }
    __syncthreads();
    if (wid == 0) TC_DEALLOC(tmem, 128);
}

#else  // !USE_TCGEN05 — correct SIMT fallback

__device__ __forceinline__ void gemm_body(
    const __nv_bfloat16* __restrict__ Ahi, const __nv_bfloat16* __restrict__ Alo,
    const __nv_bfloat16* __restrict__ Bhi, const __nv_bfloat16* __restrict__ Blo,
    float* __restrict__ Cf, __nv_bfloat16* __restrict__ Chi, __nv_bfloat16* __restrict__ Clo,
    int outmode, int row0, int col0)
{
    extern __shared__ char smem[];
    float* arow = (float*)smem;
    const int tid = threadIdx.x;
    const int brow = row0 >> 11;
    const __nv_bfloat16* bh = Bhi + (size_t)(col0 + tid) * EMB;
    const __nv_bfloat16* bl = Blo + (size_t)(col0 + tid) * EMB;
    for (int r = 0; r < 128; ++r) {
        __syncthreads();
        for (int i = tid; i < EMB; i += 128) {
            size_t off = (size_t)(row0 + r) * EMB + i;
            arow[i] = __bfloat162float(Ahi[off]) + __bfloat162float(Alo[off]);
        }
        __syncthreads();
        float acc = 0.f;
        for (int k = 0; k < EMB; ++k)
            acc = fmaf(arow[k], __bfloat162float(bh[k]) + __bfloat162float(bl[k]), acc);
        if (outmode == 0) {
            Cf[(size_t)(row0 + r) * EMB + col0 + tid] = acc;
        } else if (outmode == 1) {
            __nv_bfloat16 h, l; bf16_split(acc, h, l);
            size_t o = (size_t)(row0 + r) * EMB + col0 + tid;
            Chi[o] = h; Clo[o] = l;
        } else {
            __nv_bfloat16 h, l; bf16_split(acc, h, l);
            size_t o = ((size_t)(brow * 1024 + col0 + tid)) * 2048 + (row0 & 2047) + r;
            Chi[o] = h; Clo[o] = l;
        }
    }
}
#endif  // USE_TCGEN05

// grid (32, 8, 3): z = 0/1/2 -> Q/K/V. V written transposed (outmode 2).
__global__ __launch_bounds__(128, 3) void gemm_qkv_kernel()
{
    int z = blockIdx.z;
    __nv_bfloat16* hi = (z == 0) ? g_qhi : (z == 1) ? g_khi : g_vthi;
    __nv_bfloat16* lo = (z == 0) ? g_qlo : (z == 1) ? g_klo : g_vtlo;
    gemm_body(g_xhi, g_xlo, g_wthi[z], g_wtlo[z], nullptr, hi, lo, (z == 2) ? 2 : 1,
              blockIdx.x * 128, blockIdx.y * 128);
}

// grid (32, 8): out = ctx @ Wo (fp32 output)
__global__ __launch_bounds__(128, 3) void gemm_out_kernel(float* __restrict__ out)
{
    gemm_body(g_chi, g_clo, g_wthi[3], g_wtlo[3], out, nullptr, nullptr, 0,
              blockIdx.x * 128, blockIdx.y * 128);
}

// ---------------------------------------------------------------------------
// Tensorized causal attention, 64-key blocks, 2 CTAs/SM (unchanged from R11).
// TMEM (alloc 256): S0 0-63 | S1 64-127 | Phi 128-159 | Plo 160-191 | O 192-255.
// ---------------------------------------------------------------------------
#if USE_TCGEN05

__global__ __launch_bounds__(256, 2) void attn_tc_kernel()
{
    extern __shared__ char smem[];
    const uint32_t sb = smem_u32(smem);
    const uint32_t tb = (sb + 1023) & ~1023u;
    const uint32_t ctl = tb + AT_TILES;

    const int tid = threadIdx.x, wid = tid >> 5, lane = tid & 31;
    const int sp = wid & 3;              // TMEM subpartition
    const int ch = wid >> 2;             // column half of 64 (0/1)
    const int bid = blockIdx.x;
    const int qtile = 15 - (bid >> 5);   // descending work
    const int hb = bid & 31;
    const int h = hb & 15, b = hb >> 4;
    const int row = sp * 32 + lane;
    const int qr = qtile * 128 + row;
    const uint32_t rbase = (uint32_t)sp << 21;

    const uint32_t QH = tb, QL = tb + 16384;

    if (wid == 0) { TC_ALLOC(ctl, 256); TC_RELINQ(); }
    if (tid == 0) { MBAR_INIT(ctl + 8, 1); MBAR_INIT(ctl + 16, 1); MBAR_INIT(ctl + 24, 1); }
    __syncthreads();
    uint32_t tmem;
    asm volatile("ld.shared.b32 %0, [%1];" : "=r"(tmem) : "r"(ctl));

    const uint32_t IDESC = (1u << 4) | (1u << 7) | (1u << 10) | (8u << 17) | (8u << 24);
    const uint32_t PH_COL = 128, PL_COL = 160, O_COL = 192;

    const size_t khead = (size_t)(b * SEQ) * EMB + h * HDIM;
    const size_t vhead = (size_t)((b * HEADS + h) * HDIM) * SEQ;
    const int ntk = 2 * qtile + 2;       // 64-key blocks

    auto load_k = [&](int kb, uint32_t ks) {
        const size_t base = khead + (size_t)(kb * 64) * EMB;
        #pragma unroll
        for (int i = 0; i < 2; ++i) {
            int idx = i * 256 + tid;
            int r = idx >> 3, u = idx & 7;
            uint32_t dst = SMEM_SWZ128((uint32_t)(r * 128 + u * 16));
            size_t off = base + (size_t)r * EMB + u * 8;
            CP_ASYNC16(ks + dst,        g_khi + off);
            CP_ASYNC16(ks + 8192 + dst, g_klo + off);
        }
    };
    auto load_v = [&](int kb, uint32_t vs) {
        const size_t base = vhead + kb * 64;
        #pragma unroll
        for (int i = 0; i < 2; ++i) {
            int idx = i * 256 + tid;
            int r = idx >> 3, u = idx & 7;
            uint32_t dst = SMEM_SWZ128((uint32_t)(r * 128 + u * 16));
            size_t off = base + (size_t)r * SEQ + u * 8;
            CP_ASYNC16(vs + dst,        g_vthi + off);
            CP_ASYNC16(vs + 8192 + dst, g_vtlo + off);
        }
    };

    auto issue_smma = [&](uint32_t d, uint32_t ks) {
        uint64_t qhd = MAKE_DESC(QH), qld = MAKE_DESC(QL);
        uint64_t khd = MAKE_DESC(ks), kld = MAKE_DESC(ks + 8192);
        #pragma unroll
        for (int s = 0; s < 4; ++s)
            mma_f16_ss(d, qhd + s * 2, khd + s * 2, IDESC, s > 0 ? 1u : 0u);
        #pragma unroll
        for (int s = 0; s < 4; ++s)
            mma_f16_ss(d, qhd + s * 2, kld + s * 2, IDESC, 1u);
        #pragma unroll
        for (int s = 0; s < 4; ++s)
            mma_f16_ss(d, qld + s * 2, khd + s * 2, IDESC, 1u);
    };

    // ---- Preamble: Q + K(0) + V(0) [group1], K(1) [group2] ----
    {
        const __nv_bfloat16* qh = g_qhi + khead + (size_t)(qtile * 128) * EMB;
        const __nv_bfloat16* ql = g_qlo + khead + (size_t)(qtile * 128) * EMB;
        #pragma unroll
        for (int i = 0; i < 4; ++i) {
            int idx = i * 256 + tid;
            int r = idx >> 3, u = idx & 7;
            uint32_t dst = SMEM_SWZ128((uint32_t)(r * 128 + u * 16));
            size_t off = (size_t)r * EMB + u * 8;
            CP_ASYNC16(QH + dst, qh + off);
            CP_ASYNC16(QL + dst, ql + off);
        }
        load_k(0, tb + 32768);
        load_v(0, tb + 65536);
        CP_COMMIT();
        load_k(1, tb + 32768 + 16384);
        CP_COMMIT();
        CP_WAIT1();
        __syncthreads();
        FENCE_ASYNC();
    }

    if (wid == 0 && elect_one()) {
        TC_FENCE_AFTER();
        issue_smma(tmem, tb + 32768);    // S(0) -> S-buf 0
        TC_COMMIT(ctl + 8);
    }

    float lpart = 0.f;
    int ph_s0 = 0, ph_s1 = 0, ph_o = 0;

    #pragma unroll 1
    for (int kb = 0; kb < ntk; ++kb) {
        CP_WAIT0();
        __syncthreads();
        FENCE_ASYNC();
        if (kb + 1 < ntk && wid == 0 && elect_one()) {
            TC_FENCE_AFTER();
            issue_smma(tmem + ((kb + 1) & 1) * 64, tb + 32768 + ((kb + 1) & 1) * 16384);
            TC_COMMIT((kb + 1) & 1 ? ctl + 24 : ctl + 8);
        }

        if (kb & 1) { MBAR_WAIT(ctl + 24, ph_s1); ph_s1 ^= 1; }
        else        { MBAR_WAIT(ctl + 8,  ph_s0); ph_s0 ^= 1; }
        TC_FENCE_AFTER();

        uint32_t sreg[32];
        TC_LD_X32(sreg, tmem + (kb & 1) * 64 + ch * 32 + rbase);
        TC_WAIT_LD();

        if (kb + 2 < ntk) { load_k(kb + 2, tb + 32768 + (kb & 1) * 16384); CP_COMMIT(); }

        const int jg0 = kb * 64 + ch * 32;
        const bool diag = (kb >= ntk - 2);
        uint32_t phi[16], plo[16];
        float lsum = 0.f;
        #pragma unroll
        for (int c = 0; c < 16; ++c) {
            float p0 = exp2f(fmaf(__uint_as_float(sreg[2 * c]),     0.1803368801f, -17.3123405f));
            float p1 = exp2f(fmaf(__uint_as_float(sreg[2 * c + 1]), 0.1803368801f, -17.3123405f));
            if (diag) {
                if (jg0 + 2 * c     > qr) p0 = 0.f;
                if (jg0 + 2 * c + 1 > qr) p1 = 0.f;
            }
            lsum += p0 + p1;
            uint32_t u0 = __float_as_uint(p0), u1 = __float_as_uint(p1);
            float h0 = __uint_as_float(u0 & 0xffff0000u);
            float h1 = __uint_as_float(u1 & 0xffff0000u);
            phi[c] = __byte_perm(u0, u1, 0x7632);
            __nv_bfloat162 lp = __floats2bfloat162_rn(p0 - h0, p1 - h1);
            plo[c] = *reinterpret_cast<uint32_t*>(&lp);
        }
        lpart += lsum;

        if (kb > 0) { MBAR_WAIT(ctl + 16, ph_o); ph_o ^= 1; }
        if (kb + 1 < ntk) { load_v(kb + 1, tb + 65536 + ((kb + 1) & 1) * 16384); CP_COMMIT(); }

        TC_ST_X16(tmem + PH_COL + ch * 16 + rbase, phi);
        TC_ST_X16(tmem + PL_COL + ch * 16 + rbase, plo);
        TC_WAIT_ST();
        TC_FENCE_BEFORE();
        __syncthreads();

        if (wid == 0 && elect_one()) {
            TC_FENCE_AFTER();
            const uint32_t vsb = tb + 65536 + (kb & 1) * 16384;
            uint64_t vhd = MAKE_DESC(vsb);
            uint64_t vld = MAKE_DESC(vsb + 8192);
            #pragma unroll
            for (int s = 0; s < 4; ++s)
                mma_f16_ts(tmem + O_COL, tmem + PH_COL + s * 8, vhd + s * 2, IDESC,
                           (kb > 0 || s > 0) ? 1u : 0u);
            #pragma unroll
            for (int s = 0; s < 4; ++s)
                mma_f16_ts(tmem + O_COL, tmem + PH_COL + s * 8, vld + s * 2, IDESC, 1u);
            #pragma unroll
            for (int s = 0; s < 4; ++s)
                mma_f16_ts(tmem + O_COL, tmem + PL_COL + s * 8, vhd + s * 2, IDESC, 1u);
            TC_COMMIT(ctl + 16);
        }
    }

    MBAR_WAIT(ctl + 16, ph_o);
    TC_FENCE_AFTER();

    float* lred = (float*)(smem + (tb - sb));
    lred[ch * 128 + row] = lpart;
    __syncthreads();
    const float inv = 1.f / (lred[row] + lred[128 + row]);

    uint32_t oreg[32];
    TC_LD_X32(oreg, tmem + O_COL + ch * 32 + rbase);
    TC_WAIT_LD();
    {
        size_t obase = (size_t)(b * SEQ + qr) * EMB + h * HDIM + ch * 32;
        #pragma unroll
        for (int j = 0; j < 32; j += 2) {
            float v0 = __uint_as_float(oreg[j]) * inv;
            float v1 = __uint_as_float(oreg[j + 1]) * inv;
            __nv_bfloat16 h0, h1, l0, l1;
            bf16_split(v0, h0, l0); bf16_split(v1, h1, l1);
            *(__nv_bfloat162*)(g_chi + obase + j) = __halves2bfloat162(h0, h1);
            *(__nv_bfloat162*)(g_clo + obase + j) = __halves2bfloat162(l0, l1);
        }
    }
    TC_FENCE_BEFORE();
    __syncthreads();
    if (tid == 0) { MBAR_INVAL(ctl + 8); MBAR_INVAL(ctl + 16); MBAR_INVAL(ctl + 24); }
    __syncthreads();
    if (wid == 0) TC_DEALLOC(tmem, 256);
}

#else  // fallback SIMT attention (compute_103 pass only)

__global__ __launch_bounds__(256, 2) void attn_tc_kernel()
{
    const int bid = blockIdx.x;
    const int qtile = 15 - (bid >> 5);
    const int hb = bid & 31;
    const int h = hb & 15, b = hb >> 4;
    const int t = threadIdx.x;
    const int qr = qtile * 128 + (t & 127);
    const size_t headbase = (size_t)b * SEQ * EMB + (size_t)h * HDIM;
    const size_t vthead = (size_t)((b * HEADS + h) * HDIM) * SEQ;

    __shared__ float Ks[128 * HDIM];
    __shared__ float Vs[128 * HDIM];

    float q[HDIM], acc[HDIM];
    if (t < 128) {
        for (int d = 0; d < HDIM; ++d) {
            size_t off = headbase + (size_t)qr * EMB + d;
            q[d] = __bfloat162float(g_qhi[off]) + __bfloat162float(g_qlo[off]);
            acc[d] = 0.f;
        }
    }
    float l = 0.f;
    for (int kt = 0; kt <= qtile; ++kt) {
        __syncthreads();
        for (int i = t; i < 128 * HDIM; i += 256) {
            int r = i / HDIM, d = i % HDIM;
            size_t koff = headbase + (size_t)(kt * 128 + r) * EMB + d;
            Ks[i] = __bfloat162float(g_khi[koff]) + __bfloat162float(g_klo[koff]);
            size_t voff = vthead + (size_t)d * SEQ + kt * 128 + r;
            Vs[i] = __bfloat162float(g_vthi[voff]) + __bfloat162float(g_vtlo[voff]);
        }
        __syncthreads();
        if (t < 128) {
            int jmax = (kt == qtile) ? (qr - kt * 128) : 127;
            for (int j = 0; j <= jmax; ++j) {
                float s = 0.f;
                for (int d = 0; d < HDIM; ++d) s = fmaf(q[d], Ks[j * HDIM + d], s);
                float p = __expf(fmaf(s, 0.125f, -12.f));
                l += p;
                for (int d = 0; d < HDIM; ++d) acc[d] = fmaf(p, Vs[j * HDIM + d], acc[d]);
            }
        }
    }
    if (t < 128) {
        float inv = 1.f / l;
        for (int d = 0; d < HDIM; ++d) {
            __nv_bfloat16 hh, ll;
            bf16_split(acc[d] * inv, hh, ll);
            size_t off = headbase + (size_t)qr * EMB + d;
            g_chi[off] = hh;
            g_clo[off] = ll;
        }
    }
}
#endif

// ---------------------------------------------------------------------------
extern "C" void kernel_launch(void* const* d_in, const int* in_sizes, int n_in,
                              void* d_out, int out_size)
{
    const float* x  = (const float*)d_in[0];
    const float* wq = (const float*)d_in[1];
    const float* wk = (const float*)d_in[2];
    const float* wv = (const float*)d_in[3];
    const float* wo = (const float*)d_in[4];
    float* out = (float*)d_out;

    cudaFuncSetAttribute(gemm_qkv_kernel, cudaFuncAttributeMaxDynamicSharedMemorySize, SMEM_DYN);
    cudaFuncSetAttribute(gemm_out_kernel, cudaFuncAttributeMaxDynamicSharedMemorySize, SMEM_DYN);
    cudaFuncSetAttribute(attn_tc_kernel,  cudaFuncAttributeMaxDynamicSharedMemorySize, AT_SMEM);

    // 1) fp32 -> bf16 hi/lo splits (x) + all 4 weight transposes
    split_kernel<<<(MTOT * EMB / 4) / 256, 256>>>(x);
    transpose_split_kernel<<<dim3(32, 32, 4), dim3(32, 8)>>>(wq, wk, wv, wo);

    // 2) QKV projections (KC=32 ping-pong, 3 CTAs/SM); V epilogue writes V^T
    gemm_qkv_kernel<<<dim3(32, 8, 3), 128, SMEM_DYN>>>();

    // 3) Tensorized causal attention, 64-key blocks, 2 CTAs/SM
    attn_tc_kernel<<<512, 256, AT_SMEM>>>();

    // 4) Output projection (fp32 out)
    gemm_out_kernel<<<dim3(32, 8), 128, SMEM_DYN>>>(out);
}